// round 1
// baseline (speedup 1.0000x reference)
#include <cuda_runtime.h>
#include <cuda_bf16.h>
#include <math.h>

// Problem constants
#define T_DIM 1024
#define S_DIM 128
#define H_DIM 512
#define LN_EPS 1e-5f

// Scratch (allocation-free rule: __device__ globals)
__device__ float d_gt[T_DIM * H_DIM];   // text  @ wt^T   (1024 x 512)
__device__ float d_gs[S_DIM * H_DIM];   // struct @ ws^T  (128  x 512)

// ---------------------------------------------------------------------------
// GEMM: C[r,i] = sum_k A[r,k] * gate_w[i*1024 + woff + k]
// A row-major (M x 512). gate_w row-major (512 x 1024), woff selects wt/ws.
// Tiles: 64x64, K-tile 16, 256 threads, each computes 4x4.
// which==0 -> write d_gt, which==1 -> write d_gs
// ---------------------------------------------------------------------------
#define BM 64
#define BN 64
#define BK 16

__global__ __launch_bounds__(256) void gemm_tn_kernel(
    const float* __restrict__ A, const float* __restrict__ W,
    int woff, int which)
{
    __shared__ float As[BM][BK + 1];
    __shared__ float Bs[BN][BK + 1];

    float* __restrict__ C = which ? d_gs : d_gt;

    const int tx = threadIdx.x;          // 0..15 (N dir)
    const int ty = threadIdx.y;          // 0..15 (M dir)
    const int tid = ty * 16 + tx;        // 0..255
    const int brow = blockIdx.y * BM;
    const int bcol = blockIdx.x * BN;

    float acc[4][4];
    #pragma unroll
    for (int i = 0; i < 4; i++)
        #pragma unroll
        for (int j = 0; j < 4; j++) acc[i][j] = 0.f;

    for (int k0 = 0; k0 < H_DIM; k0 += BK) {
        // Load 64x16 A tile and 64x16 B tile (1024 floats each, 4 per thread)
        #pragma unroll
        for (int i = 0; i < 4; i++) {
            int idx = tid + i * 256;
            int r = idx / BK, c = idx % BK;
            As[r][c] = A[(size_t)(brow + r) * H_DIM + k0 + c];
            Bs[r][c] = W[(size_t)(bcol + r) * 1024 + woff + k0 + c];
        }
        __syncthreads();

        #pragma unroll
        for (int k = 0; k < BK; k++) {
            float a[4], b[4];
            #pragma unroll
            for (int i = 0; i < 4; i++) a[i] = As[ty * 4 + i][k];
            #pragma unroll
            for (int j = 0; j < 4; j++) b[j] = Bs[tx * 4 + j][k];
            #pragma unroll
            for (int i = 0; i < 4; i++)
                #pragma unroll
                for (int j = 0; j < 4; j++)
                    acc[i][j] = fmaf(a[i], b[j], acc[i][j]);
        }
        __syncthreads();
    }

    #pragma unroll
    for (int i = 0; i < 4; i++) {
        int r = brow + ty * 4 + i;
        #pragma unroll
        for (int j = 0; j < 4; j++) {
            int c = bcol + tx * 4 + j;
            C[(size_t)r * H_DIM + c] = acc[i][j];
        }
    }
}

// ---------------------------------------------------------------------------
// Fused: gates = relu(gt[t,h] + gs[s,h] + b[h]) * mask[t,s]
//        enrichment[t,h] = sum_s gates[t,s,h] * struct[s,h]
//        enriched = LayerNorm(text + enrichment)
// One block handles TB=4 t-rows; 512 threads = one per h.
// ---------------------------------------------------------------------------
#define TB 4

__global__ __launch_bounds__(512) void fuse_kernel(
    const float* __restrict__ text,
    const float* __restrict__ sstruct,
    const int*   __restrict__ mask,
    const float* __restrict__ gate_b,
    const float* __restrict__ gamma,
    const float* __restrict__ beta,
    float* __restrict__ enriched,   // (T, H)
    float* __restrict__ gates)      // (T, S, H)
{
    const int h  = threadIdx.x;           // 0..511
    const int t0 = blockIdx.x * TB;

    __shared__ float msk[TB][S_DIM];
    __shared__ float red[2][TB][16];

    // Load mask tile (as float 0/1)
    for (int i = h; i < TB * S_DIM; i += H_DIM) {
        int tt = i / S_DIM, s = i % S_DIM;
        msk[tt][s] = (float)mask[(size_t)(t0 + tt) * S_DIM + s];
    }
    __syncthreads();

    const float bh = gate_b[h];
    float gtb[TB], acc[TB];
    #pragma unroll
    for (int tt = 0; tt < TB; tt++) {
        gtb[tt] = d_gt[(size_t)(t0 + tt) * H_DIM + h] + bh;
        acc[tt] = 0.f;
    }

    #pragma unroll 4
    for (int s = 0; s < S_DIM; s++) {
        const float gsv = d_gs[(size_t)s * H_DIM + h];
        const float sv  = sstruct[(size_t)s * H_DIM + h];
        #pragma unroll
        for (int tt = 0; tt < TB; tt++) {
            float g = fmaxf(gtb[tt] + gsv, 0.f) * msk[tt][s];
            gates[((size_t)(t0 + tt) * S_DIM + s) * H_DIM + h] = g;
            acc[tt] = fmaf(g, sv, acc[tt]);
        }
    }

    // LayerNorm over h for each of the TB rows
    const int lane = h & 31, warp = h >> 5;
    float xv[TB];
    #pragma unroll
    for (int tt = 0; tt < TB; tt++) {
        float x = text[(size_t)(t0 + tt) * H_DIM + h] + acc[tt];
        xv[tt] = x;
        float s1 = x, s2 = x * x;
        #pragma unroll
        for (int o = 16; o > 0; o >>= 1) {
            s1 += __shfl_xor_sync(0xFFFFFFFFu, s1, o);
            s2 += __shfl_xor_sync(0xFFFFFFFFu, s2, o);
        }
        if (lane == 0) { red[0][tt][warp] = s1; red[1][tt][warp] = s2; }
    }
    __syncthreads();

    const float gm = gamma[h], bt = beta[h];
    #pragma unroll
    for (int tt = 0; tt < TB; tt++) {
        float s1 = 0.f, s2 = 0.f;
        #pragma unroll
        for (int w = 0; w < 16; w++) { s1 += red[0][tt][w]; s2 += red[1][tt][w]; }
        float mu  = s1 * (1.f / H_DIM);
        float var = s2 * (1.f / H_DIM) - mu * mu;
        float inv = rsqrtf(var + LN_EPS);
        enriched[(size_t)(t0 + tt) * H_DIM + h] = (xv[tt] - mu) * inv * gm + bt;
    }
}

// ---------------------------------------------------------------------------
// Launch
// inputs: 0 text_embeds (T,H) f32 | 1 struct_embeds (S,H) f32 | 2 mask (T,S) i32
//         3 gate_w (H,2H) f32 | 4 gate_b (H) | 5 ln_gamma (H) | 6 ln_beta (H)
// output: enriched (T*H) floats followed by gates (T*S*H) floats
// ---------------------------------------------------------------------------
extern "C" void kernel_launch(void* const* d_in, const int* in_sizes, int n_in,
                              void* d_out, int out_size)
{
    const float* text    = (const float*)d_in[0];
    const float* sstruct = (const float*)d_in[1];
    const int*   mask    = (const int*)  d_in[2];
    const float* gate_w  = (const float*)d_in[3];
    const float* gate_b  = (const float*)d_in[4];
    const float* gamma   = (const float*)d_in[5];
    const float* beta    = (const float*)d_in[6];

    float* enriched = (float*)d_out;
    float* gates    = (float*)d_out + (size_t)T_DIM * H_DIM;

    // gt = text @ wt^T   (woff=0)
    {
        dim3 blk(16, 16);
        dim3 grd(H_DIM / BN, T_DIM / BM);
        gemm_tn_kernel<<<grd, blk>>>(text, gate_w, 0, 0);
    }
    // gs = struct @ ws^T (woff=H)
    {
        dim3 blk(16, 16);
        dim3 grd(H_DIM / BN, S_DIM / BM);
        gemm_tn_kernel<<<grd, blk>>>(sstruct, gate_w, H_DIM, 1);
    }
    // fused gates + enrichment + layernorm
    {
        fuse_kernel<<<T_DIM / TB, H_DIM>>>(text, sstruct, mask,
                                           gate_b, gamma, beta,
                                           enriched, gates);
    }
}